// round 1
// baseline (speedup 1.0000x reference)
#include <cuda_runtime.h>
#include <math.h>

// Scratch for r_inv (no cudaMalloc allowed).
__device__ float g_rinv[16384];

// ---------------------------------------------------------------------------
// Kernel 1: one warp per row. Row = 8192 fp32 = 32KB, read as float4.
// Each lane accumulates 64 float4s (stride 32*4 floats), warp-shuffle reduce,
// add 1.0 for the identity diagonal, rsqrt -> g_rinv[row].
// ---------------------------------------------------------------------------
__global__ void __launch_bounds__(256) rowsum_rinv_kernel(
    const float* __restrict__ adj, int n)
{
    const int warps_per_block = blockDim.x >> 5;
    const int warp_id = (blockIdx.x * warps_per_block) + (threadIdx.x >> 5);
    const int lane = threadIdx.x & 31;
    if (warp_id >= n) return;

    const float4* row = reinterpret_cast<const float4*>(adj + (size_t)warp_id * n);
    const int n4 = n >> 2;  // 2048

    float s = 0.0f;
    #pragma unroll 4
    for (int c = lane; c < n4; c += 32) {
        float4 v = row[c];
        s += (v.x + v.y) + (v.z + v.w);
    }
    // warp reduce
    #pragma unroll
    for (int off = 16; off > 0; off >>= 1)
        s += __shfl_xor_sync(0xFFFFFFFFu, s, off);

    if (lane == 0) {
        float rowsum = s + 1.0f;  // + I diagonal
        g_rinv[warp_id] = (rowsum > 0.0f) ? rsqrtf(rowsum) : 0.0f;
    }
}

// ---------------------------------------------------------------------------
// Kernel 2: one block per row. out[i][j] = (adj[i][j] + (i==j)) * ri * rj
// float4 loads/stores; r_inv column vector (32KB) lives in L2.
// ---------------------------------------------------------------------------
__global__ void __launch_bounds__(256) scale_kernel(
    const float* __restrict__ adj, float* __restrict__ out, int n)
{
    const int row = blockIdx.x;
    const float ri = g_rinv[row];
    const float4* arow = reinterpret_cast<const float4*>(adj + (size_t)row * n);
    float4* orow = reinterpret_cast<float4*>(out + (size_t)row * n);
    const float4* rinv4 = reinterpret_cast<const float4*>(g_rinv);
    const int n4 = n >> 2;  // 2048

    for (int c = threadIdx.x; c < n4; c += blockDim.x) {
        float4 a = arow[c];
        float4 r = rinv4[c];
        int j0 = c << 2;
        // fold in identity diagonal branchlessly
        a.x += (j0 + 0 == row) ? 1.0f : 0.0f;
        a.y += (j0 + 1 == row) ? 1.0f : 0.0f;
        a.z += (j0 + 2 == row) ? 1.0f : 0.0f;
        a.w += (j0 + 3 == row) ? 1.0f : 0.0f;
        float4 o;
        o.x = a.x * ri * r.x;
        o.y = a.y * ri * r.y;
        o.z = a.z * ri * r.z;
        o.w = a.w * ri * r.w;
        orow[c] = o;
    }
}

extern "C" void kernel_launch(void* const* d_in, const int* in_sizes, int n_in,
                              void* d_out, int out_size)
{
    const float* adj = (const float*)d_in[0];
    float* out = (float*)d_out;

    // n x n matrix
    int n = 1;
    {
        long long total = in_sizes[0];
        // integer sqrt
        long long lo = 1, hi = 1 << 16;
        while (lo < hi) {
            long long mid = (lo + hi + 1) >> 1;
            if (mid * mid <= total) lo = mid; else hi = mid - 1;
        }
        n = (int)lo;
    }

    // Kernel 1: warp per row (8 warps / 256-thread block)
    int warps_per_block = 8;
    int blocks1 = (n + warps_per_block - 1) / warps_per_block;
    rowsum_rinv_kernel<<<blocks1, 256>>>(adj, n);

    // Kernel 2: block per row
    scale_kernel<<<n, 256>>>(adj, out, n);
}

// round 2
// speedup vs baseline: 1.0035x; 1.0035x over previous
#include <cuda_runtime.h>
#include <math.h>

// Scratch for r_inv (no cudaMalloc allowed).
__device__ float g_rinv[16384];

// ---------------------------------------------------------------------------
// Kernel 1: one warp per row. Row = 8192 fp32 = 32KB, read as float4.
// float4 accumulator (4 independent FADD chains) + unroll 8 for deep MLP.
// Rows read in increasing order so the TAIL rows stay L2-resident for kernel 2.
// ---------------------------------------------------------------------------
__global__ void __launch_bounds__(256) rowsum_rinv_kernel(
    const float* __restrict__ adj, int n)
{
    const int warps_per_block = blockDim.x >> 5;
    const int warp_id = (blockIdx.x * warps_per_block) + (threadIdx.x >> 5);
    const int lane = threadIdx.x & 31;
    if (warp_id >= n) return;

    const float4* row = reinterpret_cast<const float4*>(adj + (size_t)warp_id * n);
    const int n4 = n >> 2;  // 2048

    float4 acc = make_float4(0.f, 0.f, 0.f, 0.f);
    #pragma unroll 8
    for (int c = lane; c < n4; c += 32) {
        float4 v = row[c];
        acc.x += v.x;
        acc.y += v.y;
        acc.z += v.z;
        acc.w += v.w;
    }
    float s = (acc.x + acc.y) + (acc.z + acc.w);

    // warp reduce
    #pragma unroll
    for (int off = 16; off > 0; off >>= 1)
        s += __shfl_xor_sync(0xFFFFFFFFu, s, off);

    if (lane == 0) {
        float rowsum = s + 1.0f;  // + I diagonal
        g_rinv[warp_id] = (rowsum > 0.0f) ? rsqrtf(rowsum) : 0.0f;
    }
}

// ---------------------------------------------------------------------------
// Kernel 2: one block per row, rows processed in REVERSE order so the first
// waves read the rows kernel 1 touched last (still in L2, ~126MB window).
// __ldcs: each adj element is read exactly once -> evict-first, preserves the
// inherited residency. __stcs: output is never re-read -> don't allocate L2.
// ---------------------------------------------------------------------------
__global__ void __launch_bounds__(256) scale_kernel(
    const float* __restrict__ adj, float* __restrict__ out, int n)
{
    const int row = (n - 1) - blockIdx.x;  // reverse order
    const float ri = g_rinv[row];
    const float4* arow = reinterpret_cast<const float4*>(adj + (size_t)row * n);
    float4* orow = reinterpret_cast<float4*>(out + (size_t)row * n);
    const float4* rinv4 = reinterpret_cast<const float4*>(g_rinv);
    const int n4 = n >> 2;  // 2048

    for (int c = threadIdx.x; c < n4; c += blockDim.x) {
        float4 a = __ldcs(&arow[c]);
        float4 r = rinv4[c];      // hot 32KB vector: keep default caching
        int j0 = c << 2;
        // fold in identity diagonal branchlessly
        a.x += (j0 + 0 == row) ? 1.0f : 0.0f;
        a.y += (j0 + 1 == row) ? 1.0f : 0.0f;
        a.z += (j0 + 2 == row) ? 1.0f : 0.0f;
        a.w += (j0 + 3 == row) ? 1.0f : 0.0f;
        float4 o;
        o.x = a.x * ri * r.x;
        o.y = a.y * ri * r.y;
        o.z = a.z * ri * r.z;
        o.w = a.w * ri * r.w;
        __stcs(&orow[c], o);
    }
}

extern "C" void kernel_launch(void* const* d_in, const int* in_sizes, int n_in,
                              void* d_out, int out_size)
{
    const float* adj = (const float*)d_in[0];
    float* out = (float*)d_out;

    // n x n matrix
    int n = 1;
    {
        long long total = in_sizes[0];
        long long lo = 1, hi = 1 << 16;
        while (lo < hi) {
            long long mid = (lo + hi + 1) >> 1;
            if (mid * mid <= total) lo = mid; else hi = mid - 1;
        }
        n = (int)lo;
    }

    // Kernel 1: warp per row (8 warps / 256-thread block)
    int warps_per_block = 8;
    int blocks1 = (n + warps_per_block - 1) / warps_per_block;
    rowsum_rinv_kernel<<<blocks1, 256>>>(adj, n);

    // Kernel 2: block per row (reversed inside kernel)
    scale_kernel<<<n, 256>>>(adj, out, n);
}